// round 1
// baseline (speedup 1.0000x reference)
#include <cuda_runtime.h>

#define D_  1024
#define H_  16
#define HD_ 64
#define B_  2
#define S_  2048
#define M_  (B_*S_)   // 4096

// ---------------- scratch (no allocations allowed) ----------------
__device__ float g_q[B_*H_*S_*HD_];     // [B,H,S,HD]
__device__ float g_k[B_*H_*S_*HD_];
__device__ float g_v[B_*H_*S_*HD_];
__device__ float g_attn[B_*S_*D_];      // [B,S,D]

// ---------------- 64x64 register-blocked SGEMM ----------------
#define BM 64
#define BN 64
#define BK 16

template<bool HEAD_LAYOUT>
__device__ __forceinline__ void gemm_body(const float* __restrict__ X,
                                          const float* __restrict__ W,
                                          const float* __restrict__ bias,
                                          float* __restrict__ out)
{
    __shared__ float As[BK][BM + 4];   // A transposed: As[k][m], padded row (68*4B = 16B-aligned rows)
    __shared__ float Bs[BK][BN];

    const int tid = threadIdx.x;
    const int tx = tid & 15;
    const int ty = tid >> 4;

    const int row0 = blockIdx.y * BM;
    const int col0 = blockIdx.x * BN;

    float acc[4][4] = {};

    // A tile load map: 256 threads, each one float4 of a 64x16 tile
    const int arow = tid >> 2;          // 0..63
    const int aq   = (tid & 3) * 4;     // k offset 0,4,8,12
    // B tile load map: 16x64 tile, each thread one float4
    const int brow = tid >> 4;          // 0..15
    const int bq   = (tid & 15) * 4;    // n offset

    for (int k0 = 0; k0 < D_; k0 += BK) {
        float4 av = *reinterpret_cast<const float4*>(&X[(row0 + arow) * D_ + k0 + aq]);
        As[aq + 0][arow] = av.x;
        As[aq + 1][arow] = av.y;
        As[aq + 2][arow] = av.z;
        As[aq + 3][arow] = av.w;
        *reinterpret_cast<float4*>(&Bs[brow][bq]) =
            *reinterpret_cast<const float4*>(&W[(k0 + brow) * D_ + col0 + bq]);
        __syncthreads();

        #pragma unroll
        for (int kk = 0; kk < BK; kk++) {
            float4 a = *reinterpret_cast<const float4*>(&As[kk][ty * 4]);
            float4 b = *reinterpret_cast<const float4*>(&Bs[kk][tx * 4]);
            acc[0][0] += a.x * b.x; acc[0][1] += a.x * b.y; acc[0][2] += a.x * b.z; acc[0][3] += a.x * b.w;
            acc[1][0] += a.y * b.x; acc[1][1] += a.y * b.y; acc[1][2] += a.y * b.z; acc[1][3] += a.y * b.w;
            acc[2][0] += a.z * b.x; acc[2][1] += a.z * b.y; acc[2][2] += a.z * b.z; acc[2][3] += a.z * b.w;
            acc[3][0] += a.w * b.x; acc[3][1] += a.w * b.y; acc[3][2] += a.w * b.z; acc[3][3] += a.w * b.w;
        }
        __syncthreads();
    }

    #pragma unroll
    for (int i = 0; i < 4; i++) {
        const int m = row0 + ty * 4 + i;
        #pragma unroll
        for (int j = 0; j < 4; j++) {
            const int n = col0 + tx * 4 + j;
            const float v = acc[i][j] + bias[n];
            if (HEAD_LAYOUT) {
                const int b = m >> 11;          // / S_
                const int s = m & (S_ - 1);
                const int h = n >> 6;           // / HD_
                const int hd = n & (HD_ - 1);
                out[((b * H_ + h) * S_ + s) * HD_ + hd] = v;
            } else {
                out[m * D_ + n] = v;
            }
        }
    }
}

__global__ void __launch_bounds__(256)
qkv_kernel(const float* __restrict__ X,
           const float* __restrict__ Wq, const float* __restrict__ bq,
           const float* __restrict__ Wk, const float* __restrict__ bk,
           const float* __restrict__ Wv, const float* __restrict__ bv)
{
    const int g = blockIdx.z;
    const float* W    = (g == 0) ? Wq : (g == 1) ? Wk : Wv;
    const float* bias = (g == 0) ? bq : (g == 1) ? bk : bv;
    float* out        = (g == 0) ? g_q : (g == 1) ? g_k : g_v;
    gemm_body<true>(X, W, bias, out);
}

__global__ void __launch_bounds__(256)
out_kernel(const float* __restrict__ Wo, const float* __restrict__ bo,
           float* __restrict__ out)
{
    gemm_body<false>(g_attn, Wo, bo, out);
}

// ---------------- flash attention: 64 q-rows per block ----------------
// shared: Qs[64][64], KV[64][65] (padded), Ps[64][64]  -> 49408 B dynamic
__global__ void __launch_bounds__(256)
attn_kernel()
{
    extern __shared__ float sh[];
    float* Qs = sh;                 // 64*64
    float* KV = sh + 64 * 64;       // 64*65 (padded rows)
    float* Ps = KV + 64 * 65;       // 64*64

    const int tid = threadIdx.x;
    const int tx = tid & 15;
    const int ty = tid >> 4;

    const int bh = blockIdx.y;      // b*H + h
    const int qt = blockIdx.x;      // q tile (0..31)

    const float* Qg = g_q + (size_t)bh * S_ * HD_ + qt * 64 * HD_;
    const float* Kg = g_k + (size_t)bh * S_ * HD_;
    const float* Vg = g_v + (size_t)bh * S_ * HD_;

    // Q tile is a contiguous 4096-float block
    for (int idx = tid * 4; idx < 64 * 64; idx += 256 * 4)
        *reinterpret_cast<float4*>(&Qs[idx]) = *reinterpret_cast<const float4*>(&Qg[idx]);

    float m_run[4], l_run[4], o[4][4];
    #pragma unroll
    for (int i = 0; i < 4; i++) {
        m_run[i] = -1e30f;
        l_run[i] = 0.f;
        #pragma unroll
        for (int j = 0; j < 4; j++) o[i][j] = 0.f;
    }
    const float scale = 0.125f;     // 1/sqrt(64)

    for (int t = 0; t < S_ / 64; t++) {
        // ---- load K tile into padded KV ----
        for (int idx = tid * 4; idx < 4096; idx += 1024) {
            float4 v = *reinterpret_cast<const float4*>(&Kg[t * 4096 + idx]);
            const int r = idx >> 6, c = idx & 63;
            KV[r * 65 + c + 0] = v.x;
            KV[r * 65 + c + 1] = v.y;
            KV[r * 65 + c + 2] = v.z;
            KV[r * 65 + c + 3] = v.w;
        }
        __syncthreads();

        // ---- S = Q * K^T (rows ty*4.., keys tx*4..) ----
        float s[4][4] = {};
        #pragma unroll 4
        for (int d4 = 0; d4 < 16; d4++) {
            float q[4][4];
            #pragma unroll
            for (int i = 0; i < 4; i++)
                *reinterpret_cast<float4*>(q[i]) =
                    *reinterpret_cast<const float4*>(&Qs[(ty * 4 + i) * 64 + d4 * 4]);
            #pragma unroll
            for (int dd = 0; dd < 4; dd++) {
                float kv[4];
                #pragma unroll
                for (int j = 0; j < 4; j++)
                    kv[j] = KV[(tx * 4 + j) * 65 + d4 * 4 + dd];
                #pragma unroll
                for (int i = 0; i < 4; i++)
                    #pragma unroll
                    for (int j = 0; j < 4; j++)
                        s[i][j] += q[i][dd] * kv[j];
            }
        }

        // ---- online softmax update (reduce across 16 tx lanes via shfl) ----
        #pragma unroll
        for (int i = 0; i < 4; i++) {
            float mx = s[i][0] * scale;
            #pragma unroll
            for (int j = 0; j < 4; j++) { s[i][j] *= scale; mx = fmaxf(mx, s[i][j]); }
            #pragma unroll
            for (int off = 1; off < 16; off <<= 1)
                mx = fmaxf(mx, __shfl_xor_sync(0xffffffffu, mx, off));
            const float mnew = fmaxf(m_run[i], mx);
            const float al = __expf(m_run[i] - mnew);
            float sum = 0.f;
            #pragma unroll
            for (int j = 0; j < 4; j++) {
                const float p = __expf(s[i][j] - mnew);
                s[i][j] = p;
                sum += p;
            }
            #pragma unroll
            for (int off = 1; off < 16; off <<= 1)
                sum += __shfl_xor_sync(0xffffffffu, sum, off);
            l_run[i] = l_run[i] * al + sum;
            m_run[i] = mnew;
            #pragma unroll
            for (int j = 0; j < 4; j++) o[i][j] *= al;
        }

        // write P
        #pragma unroll
        for (int i = 0; i < 4; i++)
            #pragma unroll
            for (int j = 0; j < 4; j++)
                Ps[(ty * 4 + i) * 64 + tx * 4 + j] = s[i][j];
        __syncthreads();   // done reading K, P visible

        // ---- load V tile into KV ----
        for (int idx = tid * 4; idx < 4096; idx += 1024) {
            float4 v = *reinterpret_cast<const float4*>(&Vg[t * 4096 + idx]);
            const int r = idx >> 6, c = idx & 63;
            KV[r * 65 + c + 0] = v.x;
            KV[r * 65 + c + 1] = v.y;
            KV[r * 65 + c + 2] = v.z;
            KV[r * 65 + c + 3] = v.w;
        }
        __syncthreads();

        // ---- O += P * V ----
        #pragma unroll 4
        for (int t4 = 0; t4 < 16; t4++) {
            float p[4][4];
            #pragma unroll
            for (int i = 0; i < 4; i++)
                *reinterpret_cast<float4*>(p[i]) =
                    *reinterpret_cast<const float4*>(&Ps[(ty * 4 + i) * 64 + t4 * 4]);
            #pragma unroll
            for (int dt = 0; dt < 4; dt++) {
                float vv[4];
                #pragma unroll
                for (int j = 0; j < 4; j++)
                    vv[j] = KV[(t4 * 4 + dt) * 65 + tx * 4 + j];
                #pragma unroll
                for (int i = 0; i < 4; i++)
                    #pragma unroll
                    for (int j = 0; j < 4; j++)
                        o[i][j] += p[i][dt] * vv[j];
            }
        }
        __syncthreads();   // done reading V/P before next K load
    }

    // ---- normalize and write to g_attn [B,S,D] ----
    const int b = bh >> 4;
    const int h = bh & 15;
    #pragma unroll
    for (int i = 0; i < 4; i++) {
        const float inv = 1.f / l_run[i];
        const int q = qt * 64 + ty * 4 + i;
        #pragma unroll
        for (int j = 0; j < 4; j++) {
            const int d = tx * 4 + j;
            g_attn[((size_t)b * S_ + q) * D_ + h * HD_ + d] = o[i][j] * inv;
        }
    }
}

// ---------------- launch ----------------
extern "C" void kernel_launch(void* const* d_in, const int* in_sizes, int n_in,
                              void* d_out, int out_size)
{
    const float* X  = (const float*)d_in[0];
    const float* Wq = (const float*)d_in[1];
    const float* bq = (const float*)d_in[2];
    const float* Wk = (const float*)d_in[3];
    const float* bk = (const float*)d_in[4];
    const float* Wv = (const float*)d_in[5];
    const float* bv = (const float*)d_in[6];
    const float* Wo = (const float*)d_in[7];
    const float* bo = (const float*)d_in[8];
    float* out = (float*)d_out;

    // QKV projections: N tiles x M tiles x {q,k,v}
    qkv_kernel<<<dim3(D_ / BN, M_ / BM, 3), 256>>>(X, Wq, bq, Wk, bk, Wv, bv);

    // attention
    const int shmem = (64 * 64 + 64 * 65 + 64 * 64) * (int)sizeof(float); // 49408
    cudaFuncSetAttribute(attn_kernel, cudaFuncAttributeMaxDynamicSharedMemorySize, shmem);
    attn_kernel<<<dim3(S_ / 64, B_ * H_), 256, shmem>>>();

    // output projection
    out_kernel<<<dim3(D_ / BN, M_ / BM), 256>>>(Wo, bo, out);
}

// round 3
// speedup vs baseline: 3.9080x; 3.9080x over previous
#include <cuda_runtime.h>
#include <cuda_bf16.h>
#include <cstdint>

#define D_  1024
#define H_  16
#define HD_ 64
#define B_  2
#define S_  2048
#define M_  (B_*S_)   // 4096

// ---------------- scratch (no allocations allowed) ----------------
__device__ float g_q[B_*H_*S_*HD_];     // [B,H,S,HD]
__device__ float g_k[B_*H_*S_*HD_];
__device__ float g_v[B_*H_*S_*HD_];
__device__ float g_attn[B_*S_*D_];      // [B,S,D]
__device__ float g_wt[4*D_*D_];         // transposed weights [N,K] x4

// ================= helpers =================
__device__ __forceinline__ uint32_t smem_u32(const void* p){
    uint32_t a;
    asm("{ .reg .u64 t; cvta.to.shared.u64 t, %1; cvt.u32.u64 %0, t; }":"=r"(a):"l"(p));
    return a;
}
__device__ __forceinline__ float ex2f(float x){
    float y; asm("ex2.approx.ftz.f32 %0, %1;":"=f"(y):"f"(x)); return y;
}
__device__ __forceinline__ uint32_t bfpack(float x, float y){
    __nv_bfloat162 t = __floats2bfloat162_rn(x, y);
    return *reinterpret_cast<uint32_t*>(&t);
}
// split (x,y) into bf16 hi pair + bf16 lo pair
__device__ __forceinline__ void split2(float x, float y, uint32_t& hi, uint32_t& lo){
    __nv_bfloat16 hx = __float2bfloat16_rn(x), hy = __float2bfloat16_rn(y);
    __nv_bfloat162 hh; hh.x = hx; hh.y = hy;
    hi = *reinterpret_cast<uint32_t*>(&hh);
    lo = bfpack(x - __bfloat162float(hx), y - __bfloat162float(hy));
}

#define LDSM4(R,A)  asm volatile("ldmatrix.sync.aligned.m8n8.x4.shared.b16 {%0,%1,%2,%3}, [%4];" \
    :"=r"((R)[0]),"=r"((R)[1]),"=r"((R)[2]),"=r"((R)[3]):"r"(A))
#define LDSM2(R,A)  asm volatile("ldmatrix.sync.aligned.m8n8.x2.shared.b16 {%0,%1}, [%2];" \
    :"=r"((R)[0]),"=r"((R)[1]):"r"(A))
#define LDSM2T(R,A) asm volatile("ldmatrix.sync.aligned.m8n8.x2.trans.shared.b16 {%0,%1}, [%2];" \
    :"=r"((R)[0]),"=r"((R)[1]):"r"(A))
#define MMA16816(C,A,Bv) asm volatile( \
    "mma.sync.aligned.m16n8k16.row.col.f32.bf16.bf16.f32 {%0,%1,%2,%3},{%4,%5,%6,%7},{%8,%9},{%0,%1,%2,%3};" \
    :"+f"((C)[0]),"+f"((C)[1]),"+f"((C)[2]),"+f"((C)[3]) \
    :"r"((A)[0]),"r"((A)[1]),"r"((A)[2]),"r"((A)[3]),"r"((Bv)[0]),"r"((Bv)[1]))

// ================= weight transpose: Wt[n*D+k] = W[k*D+n] =================
__global__ void __launch_bounds__(256)
transpose_w(const float* __restrict__ Wq, const float* __restrict__ Wk,
            const float* __restrict__ Wv, const float* __restrict__ Wo)
{
    __shared__ float t[32][33];
    const int z = blockIdx.z;
    const float* W = (z==0)?Wq:(z==1)?Wk:(z==2)?Wv:Wo;
    float* O = g_wt + (size_t)z*D_*D_;
    const int bx = blockIdx.x*32, by = blockIdx.y*32;
    const int tx = threadIdx.x&31, ty = threadIdx.x>>5;
    #pragma unroll
    for (int r=0;r<32;r+=8) t[ty+r][tx] = W[(size_t)(by+ty+r)*D_ + bx+tx];
    __syncthreads();
    #pragma unroll
    for (int r=0;r<32;r+=8) O[(size_t)(bx+ty+r)*D_ + by+tx] = t[tx][ty+r];
}

// ================= bf16x3 mma.sync GEMM: C[M,N] = A[M,K] * Bt[N,K]^T + bias =================
// CTA tile 128x128, k-chunk 32, double-buffered smem, 8 warps (4m x 2n, warp 32x64).
// smem per stage: Ahi(10240) Alo(10240) Bhi(10240) Blo(10240); row stride 80B (40 bf16).
#define GSTRIDE 80
#define GA_LO 10240
#define GB_HI 20480
#define GB_LO 30720
#define GSTAGE 40960
#define GSMEM (2*GSTAGE)

template<bool HEAD>
__device__ __forceinline__ void gemm_mma(const float* __restrict__ A,
                                         const float* __restrict__ Bt,
                                         const float* __restrict__ bias,
                                         float* __restrict__ out)
{
    extern __shared__ __align__(128) char sm[];
    const uint32_t su = smem_u32(sm);
    const int tid = threadIdx.x, l = tid&31, w = tid>>5;
    const int wm = (w&3)*32, wn = (w>>2)*64;
    const int m0 = blockIdx.y*128, n0 = blockIdx.x*128;
    const float* Ag = A  + (size_t)m0*D_;
    const float* Bg = Bt + (size_t)n0*D_;

    const int rb = tid>>3, kg = tid&7;
    float4 ra[4], rbv[4];

    float C[2][8][4];
    #pragma unroll
    for (int mt=0;mt<2;mt++)
        #pragma unroll
        for (int nt=0;nt<8;nt++)
            #pragma unroll
            for (int j=0;j<4;j++) C[mt][nt][j]=0.f;

    #define G_LDG(c) do{ \
        _Pragma("unroll") for (int r=0;r<4;r++){ \
            ra [r] = *reinterpret_cast<const float4*>(Ag + (size_t)(rb+32*r)*D_ + (c)*32 + kg*4); \
            rbv[r] = *reinterpret_cast<const float4*>(Bg + (size_t)(rb+32*r)*D_ + (c)*32 + kg*4); } }while(0)
    #define G_STS(s) do{ char* _b = sm + (s)*GSTAGE; \
        _Pragma("unroll") for (int r=0;r<4;r++){ \
            const int _off = (rb+32*r)*GSTRIDE + kg*8; \
            uint2 h,lo; \
            split2(ra[r].x, ra[r].y, h.x, lo.x); split2(ra[r].z, ra[r].w, h.y, lo.y); \
            *reinterpret_cast<uint2*>(_b +         _off) = h; \
            *reinterpret_cast<uint2*>(_b + GA_LO + _off) = lo; \
            split2(rbv[r].x, rbv[r].y, h.x, lo.x); split2(rbv[r].z, rbv[r].w, h.y, lo.y); \
            *reinterpret_cast<uint2*>(_b + GB_HI + _off) = h; \
            *reinterpret_cast<uint2*>(_b + GB_LO + _off) = lo; } }while(0)

    G_LDG(0); G_STS(0); G_LDG(1);
    __syncthreads();

    const uint32_t aoff = (uint32_t)((wm + (l&15))*GSTRIDE + (l>>4)*16);
    const uint32_t boff = (uint32_t)((wn + (l&7))*GSTRIDE + ((l>>3)&1)*16);

    for (int c=0;c<32;c++){
        const uint32_t sb = su + (uint32_t)(c&1)*GSTAGE;
        #pragma unroll
        for (int ks=0;ks<2;ks++){
            uint32_t ah[2][4], al[2][4];
            #pragma unroll
            for (int mt=0;mt<2;mt++){
                const uint32_t a = sb + aoff + mt*(16*GSTRIDE) + ks*32;
                LDSM4(ah[mt], a);
                LDSM4(al[mt], a + GA_LO);
            }
            #pragma unroll
            for (int nt=0;nt<8;nt++){
                uint32_t bh[2], bl[2];
                const uint32_t ba = sb + GB_HI + boff + nt*(8*GSTRIDE) + ks*32;
                LDSM2(bh, ba);
                LDSM2(bl, ba + (GB_LO-GB_HI));
                #pragma unroll
                for (int mt=0;mt<2;mt++){
                    MMA16816(C[mt][nt], ah[mt], bh);
                    MMA16816(C[mt][nt], ah[mt], bl);
                    MMA16816(C[mt][nt], al[mt], bh);
                }
            }
        }
        __syncthreads();
        if (c < 31){
            G_STS((c+1)&1);
            if (c < 30) G_LDG(c+2);
            __syncthreads();
        }
    }

    #pragma unroll
    for (int mt=0;mt<2;mt++){
        #pragma unroll
        for (int nt=0;nt<8;nt++){
            const int col = n0 + wn + nt*8 + (l&3)*2;
            const float bx = bias[col], by = bias[col+1];
            #pragma unroll
            for (int hh=0;hh<2;hh++){
                const int row = m0 + wm + mt*16 + (l>>2) + hh*8;
                float2 v; v.x = C[mt][nt][hh*2+0] + bx; v.y = C[mt][nt][hh*2+1] + by;
                if (HEAD){
                    const int b = row>>11, sq = row&(S_-1);
                    const int hd_h = col>>6, hd = col&(HD_-1);
                    *reinterpret_cast<float2*>(&out[(((size_t)b*H_+hd_h)*S_+sq)*HD_+hd]) = v;
                } else {
                    *reinterpret_cast<float2*>(&out[(size_t)row*D_ + col]) = v;
                }
            }
        }
    }
    #undef G_LDG
    #undef G_STS
}

__global__ void __launch_bounds__(256)
qkv_mma(const float* __restrict__ X, const float* __restrict__ bq,
        const float* __restrict__ bk, const float* __restrict__ bv)
{
    const int z = blockIdx.z;
    const float* bias = (z==0)?bq:(z==1)?bk:bv;
    float* out = (z==0)?g_q:(z==1)?g_k:g_v;
    gemm_mma<true>(X, g_wt + (size_t)z*D_*D_, bias, out);
}

__global__ void __launch_bounds__(256)
out_mma(const float* __restrict__ bo, float* __restrict__ out)
{
    gemm_mma<false>(g_attn, g_wt + (size_t)3*D_*D_, bo, out);
}

// ================= flash attention with mma.sync =================
// CTA: 128 q-rows of one (b,h). 8 warps, warp = m16 x n64. K tiles of 64 keys.
// smem: Q hi/lo (128x64, stride 144B), K/V hi/lo double-buffered (64x64 each).
#define ASTRIDE 144
#define AQ_LO 18432
#define AKV0  36864
#define AK_LO  9216
#define AV_HI 18432
#define AV_LO 27648
#define ASTAGE 36864
#define ASMEM (AKV0 + 2*ASTAGE)   // 110592

__global__ void __launch_bounds__(256)
attn_mma()
{
    extern __shared__ __align__(128) char sm[];
    const uint32_t su = smem_u32(sm);
    const int tid = threadIdx.x, l = tid&31, w = tid>>5;
    const int bhid = blockIdx.y, qt = blockIdx.x;
    const int wm = w*16;

    const float* Qg = g_q + (size_t)bhid*S_*HD_ + (size_t)qt*128*HD_;
    const float* Kg = g_k + (size_t)bhid*S_*HD_;
    const float* Vg = g_v + (size_t)bhid*S_*HD_;

    // ---- Q load + split (128 x 64) ----
    {
        const int row = tid>>1, c0 = (tid&1)*8;
        #pragma unroll
        for (int j=0;j<8;j++){
            float4 v = *reinterpret_cast<const float4*>(Qg + row*HD_ + (c0+j)*4);
            uint2 h, lo;
            split2(v.x, v.y, h.x, lo.x); split2(v.z, v.w, h.y, lo.y);
            const int off = row*ASTRIDE + (c0+j)*8;
            *reinterpret_cast<uint2*>(sm +         off) = h;
            *reinterpret_cast<uint2*>(sm + AQ_LO + off) = lo;
        }
    }

    const int kvrow = tid>>2, fg = tid&3;
    float4 rk[4], rv[4];
    #define A_LDG(c) do{ \
        _Pragma("unroll") for (int j=0;j<4;j++){ \
            rk[j] = *reinterpret_cast<const float4*>(Kg + (size_t)(c)*4096 + kvrow*HD_ + (fg*4+j)*4); \
            rv[j] = *reinterpret_cast<const float4*>(Vg + (size_t)(c)*4096 + kvrow*HD_ + (fg*4+j)*4); } }while(0)
    #define A_STS(s) do{ char* _b = sm + AKV0 + (s)*ASTAGE; \
        _Pragma("unroll") for (int j=0;j<4;j++){ \
            const int _off = kvrow*ASTRIDE + (fg*4+j)*8; \
            uint2 h, lo; \
            split2(rk[j].x, rk[j].y, h.x, lo.x); split2(rk[j].z, rk[j].w, h.y, lo.y); \
            *reinterpret_cast<uint2*>(_b +         _off) = h; \
            *reinterpret_cast<uint2*>(_b + AK_LO + _off) = lo; \
            split2(rv[j].x, rv[j].y, h.x, lo.x); split2(rv[j].z, rv[j].w, h.y, lo.y); \
            *reinterpret_cast<uint2*>(_b + AV_HI + _off) = h; \
            *reinterpret_cast<uint2*>(_b + AV_LO + _off) = lo; } }while(0)

    A_LDG(0); A_STS(0); A_LDG(1);
    __syncthreads();

    // ---- Q fragments to registers (kept for the whole CTA) ----
    uint32_t qh[4][4], ql[4][4];
    const uint32_t qoff = (uint32_t)((wm + (l&15))*ASTRIDE + (l>>4)*16);
    #pragma unroll
    for (int ks=0;ks<4;ks++){
        LDSM4(qh[ks], su + qoff + ks*32);
        LDSM4(ql[ks], su + AQ_LO + qoff + ks*32);
    }

    float O[8][4];
    #pragma unroll
    for (int nt=0;nt<8;nt++){ O[nt][0]=0.f; O[nt][1]=0.f; O[nt][2]=0.f; O[nt][3]=0.f; }
    float mrun[2] = {-1e30f, -1e30f}, lrun[2] = {0.f, 0.f};
    const float SC = 0.18033688011f;   // 0.125 * log2(e)

    const uint32_t koff = (uint32_t)(((l&7))*ASTRIDE + ((l>>3)&1)*16);
    const uint32_t voff = (uint32_t)((l&15)*ASTRIDE);

    for (int it=0; it<S_/64; ++it){
        const uint32_t sb = su + AKV0 + (uint32_t)(it&1)*ASTAGE;

        // ---- S = Q @ K^T ----
        float Sv[8][4];
        #pragma unroll
        for (int nt=0;nt<8;nt++){ Sv[nt][0]=0.f; Sv[nt][1]=0.f; Sv[nt][2]=0.f; Sv[nt][3]=0.f; }
        #pragma unroll
        for (int ks=0;ks<4;ks++){
            #pragma unroll
            for (int nt=0;nt<8;nt++){
                uint32_t bh[2], bl[2];
                const uint32_t ba = sb + koff + nt*(8*ASTRIDE) + ks*32;
                LDSM2(bh, ba);
                LDSM2(bl, ba + AK_LO);
                MMA16816(Sv[nt], qh[ks], bh);
                MMA16816(Sv[nt], qh[ks], bl);
                MMA16816(Sv[nt], ql[ks], bh);
            }
        }

        // ---- online softmax (rows: regs {0,1}=r, {2,3}=r+8; quad lanes share rows) ----
        #pragma unroll
        for (int hh=0;hh<2;hh++){
            const int i0 = hh*2;
            float rm = Sv[0][i0];
            #pragma unroll
            for (int nt=0;nt<8;nt++){ rm = fmaxf(rm, Sv[nt][i0]); rm = fmaxf(rm, Sv[nt][i0+1]); }
            rm = fmaxf(rm, __shfl_xor_sync(0xffffffffu, rm, 1));
            rm = fmaxf(rm, __shfl_xor_sync(0xffffffffu, rm, 2));
            const float mn = fmaxf(mrun[hh], rm);
            const float al = ex2f((mrun[hh]-mn)*SC);
            mrun[hh] = mn;
            float sum = 0.f;
            #pragma unroll
            for (int nt=0;nt<8;nt++){
                Sv[nt][i0]   = ex2f((Sv[nt][i0]  -mn)*SC); sum += Sv[nt][i0];
                Sv[nt][i0+1] = ex2f((Sv[nt][i0+1]-mn)*SC); sum += Sv[nt][i0+1];
            }
            sum += __shfl_xor_sync(0xffffffffu, sum, 1);
            sum += __shfl_xor_sync(0xffffffffu, sum, 2);
            lrun[hh] = lrun[hh]*al + sum;
            #pragma unroll
            for (int nt=0;nt<8;nt++){ O[nt][i0] *= al; O[nt][i0+1] *= al; }
        }

        // ---- O += P @ V  (P from registers; V via ldmatrix.trans) ----
        #pragma unroll
        for (int kt=0;kt<4;kt++){
            uint32_t ph[4], pl[4];
            split2(Sv[2*kt][0],   Sv[2*kt][1],   ph[0], pl[0]);
            split2(Sv[2*kt][2],   Sv[2*kt][3],   ph[1], pl[1]);
            split2(Sv[2*kt+1][0], Sv[2*kt+1][1], ph[2], pl[2]);
            split2(Sv[2*kt+1][2], Sv[2*kt+1][3], ph[3], pl[3]);
            #pragma unroll
            for (int nt=0;nt<8;nt++){
                uint32_t vh[2], vl[2];
                const uint32_t va = sb + AV_HI + voff + kt*(16*ASTRIDE) + nt*16;
                LDSM2T(vh, va);
                LDSM2T(vl, va + (AV_LO-AV_HI));
                MMA16816(O[nt], ph, vh);
                MMA16816(O[nt], ph, vl);
                MMA16816(O[nt], pl, vh);
            }
        }

        __syncthreads();
        if (it < S_/64 - 1){
            A_STS((it+1)&1);
            if (it < S_/64 - 2) A_LDG(it+2);
            __syncthreads();
        }
    }

    // ---- normalize + write to g_attn [B,S,D] ----
    const int b = bhid>>4, hhead = bhid&15;
    #pragma unroll
    for (int hh=0;hh<2;hh++){
        const float inv = 1.f / lrun[hh];
        const int row = qt*128 + wm + (l>>2) + hh*8;
        float* orow = g_attn + ((size_t)b*S_ + row)*D_ + hhead*HD_;
        #pragma unroll
        for (int nt=0;nt<8;nt++){
            float2 v; v.x = O[nt][hh*2+0]*inv; v.y = O[nt][hh*2+1]*inv;
            *reinterpret_cast<float2*>(orow + nt*8 + (l&3)*2) = v;
        }
    }
    #undef A_LDG
    #undef A_STS
}

// ---------------- launch ----------------
extern "C" void kernel_launch(void* const* d_in, const int* in_sizes, int n_in,
                              void* d_out, int out_size)
{
    const float* X  = (const float*)d_in[0];
    const float* Wq = (const float*)d_in[1];
    const float* bq = (const float*)d_in[2];
    const float* Wk = (const float*)d_in[3];
    const float* bk = (const float*)d_in[4];
    const float* Wv = (const float*)d_in[5];
    const float* bv = (const float*)d_in[6];
    const float* Wo = (const float*)d_in[7];
    const float* bo = (const float*)d_in[8];
    float* out = (float*)d_out;

    cudaFuncSetAttribute(qkv_mma,  cudaFuncAttributeMaxDynamicSharedMemorySize, GSMEM);
    cudaFuncSetAttribute(out_mma,  cudaFuncAttributeMaxDynamicSharedMemorySize, GSMEM);
    cudaFuncSetAttribute(attn_mma, cudaFuncAttributeMaxDynamicSharedMemorySize, ASMEM);

    transpose_w<<<dim3(32,32,4), 256>>>(Wq, Wk, Wv, Wo);
    qkv_mma<<<dim3(D_/128, M_/128, 3), 256, GSMEM>>>(X, bq, bk, bv);
    attn_mma<<<dim3(S_/128, B_*H_), 256, ASMEM>>>();
    out_mma<<<dim3(D_/128, M_/128), 256, GSMEM>>>(bo, out);
}

// round 4
// speedup vs baseline: 5.2574x; 1.3453x over previous
#include <cuda_runtime.h>
#include <cuda_bf16.h>
#include <cstdint>

#define D_  1024
#define H_  16
#define HD_ 64
#define B_  2
#define S_  2048
#define M_  (B_*S_)   // 4096

typedef __nv_bfloat16 bf;

// ---------------- scratch planes (bf16 hi/lo) ----------------
__device__ bf g_xh[M_*D_], g_xl[M_*D_];       // split X [B*S, D]
__device__ bf g_wh[4*D_*D_], g_wl[4*D_*D_];   // transposed W [N,K] x4
__device__ bf g_qh[M_*D_], g_ql[M_*D_];       // [B,H,S,HD]
__device__ bf g_kh[M_*D_], g_kl[M_*D_];
__device__ bf g_vh[M_*D_], g_vl[M_*D_];
__device__ bf g_ah[M_*D_], g_al[M_*D_];       // attn out [B,S,D]

// ================= helpers =================
__device__ __forceinline__ uint32_t smem_u32(const void* p){
    uint32_t a;
    asm("{ .reg .u64 t; cvta.to.shared.u64 t, %1; cvt.u32.u64 %0, t; }":"=r"(a):"l"(p));
    return a;
}
__device__ __forceinline__ float ex2f(float x){
    float y; asm("ex2.approx.ftz.f32 %0, %1;":"=f"(y):"f"(x)); return y;
}
__device__ __forceinline__ uint32_t bfpack(float x, float y){
    __nv_bfloat162 t = __floats2bfloat162_rn(x, y);
    return *reinterpret_cast<uint32_t*>(&t);
}
__device__ __forceinline__ void split2(float x, float y, uint32_t& hi, uint32_t& lo){
    __nv_bfloat16 hx = __float2bfloat16_rn(x), hy = __float2bfloat16_rn(y);
    __nv_bfloat162 hh; hh.x = hx; hh.y = hy;
    hi = *reinterpret_cast<uint32_t*>(&hh);
    lo = bfpack(x - __bfloat162float(hx), y - __bfloat162float(hy));
}

#define LDSM4(R,A)  asm volatile("ldmatrix.sync.aligned.m8n8.x4.shared.b16 {%0,%1,%2,%3}, [%4];" \
    :"=r"((R)[0]),"=r"((R)[1]),"=r"((R)[2]),"=r"((R)[3]):"r"(A))
#define LDSM4T(R,A) asm volatile("ldmatrix.sync.aligned.m8n8.x4.trans.shared.b16 {%0,%1,%2,%3}, [%4];" \
    :"=r"((R)[0]),"=r"((R)[1]),"=r"((R)[2]),"=r"((R)[3]):"r"(A))
#define MMA16816(C,A,Bv) asm volatile( \
    "mma.sync.aligned.m16n8k16.row.col.f32.bf16.bf16.f32 {%0,%1,%2,%3},{%4,%5,%6,%7},{%8,%9},{%0,%1,%2,%3};" \
    :"+f"((C)[0]),"+f"((C)[1]),"+f"((C)[2]),"+f"((C)[3]) \
    :"r"((A)[0]),"r"((A)[1]),"r"((A)[2]),"r"((A)[3]),"r"((Bv)[0]),"r"((Bv)[1]))

#define CP16(dst,src) asm volatile("cp.async.cg.shared.global [%0], [%1], 16;"::"r"(dst),"l"(src):"memory")
#define CP_COMMIT()   asm volatile("cp.async.commit_group;":::"memory")
#define CP_WAIT1()    asm volatile("cp.async.wait_group 1;":::"memory")
#define CP_WAIT0()    asm volatile("cp.async.wait_group 0;":::"memory")

// conflict-free XOR swizzles (byte offsets)
__device__ __forceinline__ uint32_t swz64 (int row, int c){ return (uint32_t)(row*64  + ((c ^ ((row>>1)&3))<<4)); }
__device__ __forceinline__ uint32_t swz128(int row, int c){ return (uint32_t)(row*128 + ((c ^ (row&7))<<4)); }

// ================= prep: split X into bf16 hi/lo planes =================
__global__ void __launch_bounds__(256)
split_x(const float* __restrict__ X)
{
    const int i0 = (blockIdx.x*256 + threadIdx.x)*8;
    float4 a = *reinterpret_cast<const float4*>(X + i0);
    float4 b = *reinterpret_cast<const float4*>(X + i0 + 4);
    uint4 h, lo;
    split2(a.x,a.y,h.x,lo.x); split2(a.z,a.w,h.y,lo.y);
    split2(b.x,b.y,h.z,lo.z); split2(b.z,b.w,h.w,lo.w);
    *reinterpret_cast<uint4*>(&g_xh[i0]) = h;
    *reinterpret_cast<uint4*>(&g_xl[i0]) = lo;
}

// ================= prep: transpose W -> bf16 hi/lo [N,K] =================
__global__ void __launch_bounds__(256)
transpose_w(const float* __restrict__ Wq, const float* __restrict__ Wk,
            const float* __restrict__ Wv, const float* __restrict__ Wo)
{
    __shared__ float t[32][33];
    const int z = blockIdx.z;
    const float* W = (z==0)?Wq:(z==1)?Wk:(z==2)?Wv:Wo;
    bf* Oh = g_wh + (size_t)z*D_*D_;
    bf* Ol = g_wl + (size_t)z*D_*D_;
    const int bx = blockIdx.x*32, by = blockIdx.y*32;
    const int tx = threadIdx.x&31, ty = threadIdx.x>>5;
    #pragma unroll
    for (int r=0;r<32;r+=8) t[ty+r][tx] = W[(size_t)(by+ty+r)*D_ + bx+tx];
    __syncthreads();
    #pragma unroll
    for (int r=0;r<32;r+=8){
        const float v = t[tx][ty+r];
        const bf h = __float2bfloat16_rn(v);
        const size_t o = (size_t)(bx+ty+r)*D_ + by+tx;
        Oh[o] = h;
        Ol[o] = __float2bfloat16_rn(v - __bfloat162float(h));
    }
}

// ================= bf16x3 GEMM: C[128,128] tile; cp.async 3-stage =================
// stage: Ah(8K) Al(8K) Bh(8K) Bl(8K) = 32KB, 64B rows swz64
#define GPLANE 8192
#define GSTG   32768
#define GSMEM  (3*GSTG)

// MODE 0: head-layout bf16 hi/lo out;  MODE 1: flat fp32 out
template<int MODE>
__device__ __forceinline__ void gemm_body(const bf* __restrict__ Ah, const bf* __restrict__ Al,
                                          const bf* __restrict__ Bh, const bf* __restrict__ Bl,
                                          const float* __restrict__ bias,
                                          float* __restrict__ outf,
                                          bf* __restrict__ oh, bf* __restrict__ ol)
{
    extern __shared__ __align__(128) char sm[];
    const uint32_t su = smem_u32(sm);
    const int tid = threadIdx.x, l = tid&31, w = tid>>5;
    const int wm = (w&3)*32, wn = (w>>2)*64;
    const int m0 = blockIdx.y*128, n0 = blockIdx.x*128;

    // cp.async mapping: plane p = tid>>6, 8 chunks/thread
    const int p = tid>>6, sub = tid&63;
    const bf* srcb = (p==0)?Ah:(p==1)?Al:(p==2)?Bh:Bl;
    const int rbase = (p<2)?m0:n0;

    #define G_ISSUE(ch) do{ \
        const uint32_t _st = su + (uint32_t)((ch)%3)*GSTG + p*GPLANE; \
        const bf* _sp = srcb + (size_t)rbase*D_ + (ch)*32; \
        _Pragma("unroll") for (int i=0;i<8;i++){ \
            const int _idx = sub + 64*i, _r = _idx>>2, _c = _idx&3; \
            CP16(_st + swz64(_r,_c), _sp + (size_t)_r*D_ + _c*8); } \
        CP_COMMIT(); }while(0)

    float C[2][8][4];
    #pragma unroll
    for (int mt=0;mt<2;mt++)
        #pragma unroll
        for (int nt=0;nt<8;nt++){ C[mt][nt][0]=0.f;C[mt][nt][1]=0.f;C[mt][nt][2]=0.f;C[mt][nt][3]=0.f; }

    G_ISSUE(0); G_ISSUE(1);

    const int g = l>>3;
    const int arow0 = wm + (l&15);
    const int brow0 = wn + ((g>>1)&1)*8 + (l&7);

    for (int c=0;c<32;c++){
        if (c<30) CP_WAIT1(); else CP_WAIT0();
        __syncthreads();
        if (c+2<32) G_ISSUE(c+2);
        const uint32_t sb = su + (uint32_t)(c%3)*GSTG;
        #pragma unroll
        for (int ks=0;ks<2;ks++){
            uint32_t ah[2][4], al2[2][4];
            #pragma unroll
            for (int mt=0;mt<2;mt++){
                const int row = arow0 + mt*16, cc = ks*2 + (l>>4);
                const uint32_t a = sb + swz64(row,cc);
                LDSM4(ah[mt], a);
                LDSM4(al2[mt], a + GPLANE);
            }
            #pragma unroll
            for (int pr=0;pr<4;pr++){
                uint32_t bh4[4], bl4[4];
                const int row = brow0 + pr*16, cc = ks*2 + (g&1);
                const uint32_t b = sb + 2*GPLANE + swz64(row,cc);
                LDSM4(bh4, b);
                LDSM4(bl4, b + GPLANE);
                #pragma unroll
                for (int s2=0;s2<2;s2++){
                    const int nt = pr*2+s2;
                    uint32_t* bh = &bh4[s2*2];
                    uint32_t* bl = &bl4[s2*2];
                    #pragma unroll
                    for (int mt=0;mt<2;mt++){
                        MMA16816(C[mt][nt], ah[mt],  bh);
                        MMA16816(C[mt][nt], ah[mt],  bl);
                        MMA16816(C[mt][nt], al2[mt], bh);
                    }
                }
            }
        }
    }

    #pragma unroll
    for (int mt=0;mt<2;mt++){
        #pragma unroll
        for (int nt=0;nt<8;nt++){
            const int col = n0 + wn + nt*8 + (l&3)*2;
            const float bx = bias[col], by = bias[col+1];
            #pragma unroll
            for (int hh=0;hh<2;hh++){
                const int row = m0 + wm + mt*16 + (l>>2) + hh*8;
                const float vx = C[mt][nt][hh*2+0] + bx;
                const float vy = C[mt][nt][hh*2+1] + by;
                if (MODE==0){
                    uint32_t h, lo; split2(vx, vy, h, lo);
                    const int b = row>>11, sq = row&(S_-1);
                    const int hd_h = col>>6, hd = col&(HD_-1);
                    const size_t o = (((size_t)b*H_+hd_h)*S_+sq)*HD_+hd;
                    *reinterpret_cast<uint32_t*>(&oh[o]) = h;
                    *reinterpret_cast<uint32_t*>(&ol[o]) = lo;
                } else {
                    float2 v; v.x = vx; v.y = vy;
                    *reinterpret_cast<float2*>(&outf[(size_t)row*D_ + col]) = v;
                }
            }
        }
    }
    #undef G_ISSUE
}

__global__ void __launch_bounds__(256,2)
qkv_k(const float* __restrict__ bq, const float* __restrict__ bk, const float* __restrict__ bv)
{
    const int z = blockIdx.z;
    const float* bias = (z==0)?bq:(z==1)?bk:bv;
    bf* oh = (z==0)?g_qh:(z==1)?g_kh:g_vh;
    bf* ol = (z==0)?g_ql:(z==1)?g_kl:g_vl;
    gemm_body<0>(g_xh, g_xl, g_wh + (size_t)z*D_*D_, g_wl + (size_t)z*D_*D_,
                 bias, nullptr, oh, ol);
}

__global__ void __launch_bounds__(256,2)
out_k(const float* __restrict__ bo, float* __restrict__ out)
{
    gemm_body<1>(g_ah, g_al, g_wh + (size_t)3*D_*D_, g_wl + (size_t)3*D_*D_,
                 bo, out, nullptr, nullptr);
}

// ================= flash attention (cp.async, 3-stage KV) =================
// smem: Qh@0 (16K), Ql@16K, KV stages @32K: Kh(8K) Kl(8K) Vh(8K) Vl(8K) x3
#define AQ   16384
#define AKV0 32768
#define ASTG 32768
#define ASMEM (AKV0 + 3*ASTG)   // 131072

__global__ void __launch_bounds__(256)
attn_k()
{
    extern __shared__ __align__(128) char sm[];
    const uint32_t su = smem_u32(sm);
    const int tid = threadIdx.x, l = tid&31, w = tid>>5;
    const int bhid = blockIdx.y, qt = blockIdx.x;
    const int wm = w*16;
    const size_t bh_off = (size_t)bhid*S_*HD_;

    // Q cp.async: 2 planes x 128 rows x 8 chunks
    {
        const int p2 = tid>>7, sub2 = tid&127;
        const bf* qs = ((p2==0)?g_qh:g_ql) + bh_off + (size_t)qt*128*HD_;
        const uint32_t qdst = su + p2*AQ;
        #pragma unroll
        for (int i=0;i<8;i++){
            const int idx = sub2 + 128*i, r = idx>>3, c = idx&7;
            CP16(qdst + swz128(r,c), qs + (size_t)r*HD_ + c*8);
        }
    }

    // KV cp.async mapping: plane p, 8 chunks/thread
    const int p = tid>>6, sub = tid&63;
    const bf* kvsrc = ((p==0)?g_kh:(p==1)?g_kl:(p==2)?g_vh:g_vl) + bh_off;
    #define A_ISSUE(it) do{ \
        const uint32_t _st = su + AKV0 + (uint32_t)((it)%3)*ASTG + p*GPLANE; \
        const bf* _sp = kvsrc + (size_t)(it)*64*HD_; \
        _Pragma("unroll") for (int i=0;i<8;i++){ \
            const int _idx = sub + 64*i, _r = _idx>>3, _c = _idx&7; \
            CP16(_st + swz128(_r,_c), _sp + (size_t)_r*HD_ + _c*8); } \
        CP_COMMIT(); }while(0)

    A_ISSUE(0);   // group 0 includes Q copies
    A_ISSUE(1);

    float O[8][4];
    #pragma unroll
    for (int nt=0;nt<8;nt++){ O[nt][0]=0.f;O[nt][1]=0.f;O[nt][2]=0.f;O[nt][3]=0.f; }
    float mrun[2] = {-1e30f,-1e30f}, lrun[2] = {0.f,0.f};
    const float SC = 0.18033688011f;   // 0.125 * log2(e)

    uint32_t qh[4][4], ql[4][4];
    const int g = l>>3;
    const int qrow = wm + (l&15);
    const int krow0 = ((g>>1)&1)*8 + (l&7);
    const int vrow0 = (l&15);

    for (int it=0; it<S_/64; ++it){
        if (it<30) CP_WAIT1(); else CP_WAIT0();
        __syncthreads();
        if (it==0){
            #pragma unroll
            for (int ks=0;ks<4;ks++){
                const uint32_t a = su + swz128(qrow, ks*2 + (l>>4));
                LDSM4(qh[ks], a);
                LDSM4(ql[ks], a + AQ);
            }
        }
        if (it+2 < S_/64) A_ISSUE(it+2);
        const uint32_t sb = su + AKV0 + (uint32_t)(it%3)*ASTG;

        // ---- S = Q @ K^T ----
        float Sv[8][4];
        #pragma unroll
        for (int nt=0;nt<8;nt++){ Sv[nt][0]=0.f;Sv[nt][1]=0.f;Sv[nt][2]=0.f;Sv[nt][3]=0.f; }
        #pragma unroll
        for (int ks=0;ks<4;ks++){
            #pragma unroll
            for (int pr=0;pr<4;pr++){
                uint32_t kh4[4], kl4[4];
                const uint32_t ka = sb + swz128(krow0 + pr*16, ks*2 + (g&1));
                LDSM4(kh4, ka);
                LDSM4(kl4, ka + GPLANE);
                #pragma unroll
                for (int s2=0;s2<2;s2++){
                    const int nt = pr*2+s2;
                    uint32_t* bh = &kh4[s2*2];
                    uint32_t* bl = &kl4[s2*2];
                    MMA16816(Sv[nt], qh[ks], bh);
                    MMA16816(Sv[nt], qh[ks], bl);
                    MMA16816(Sv[nt], ql[ks], bh);
                }
            }
        }

        // ---- online softmax ----
        #pragma unroll
        for (int hh=0;hh<2;hh++){
            const int i0 = hh*2;
            float rm = Sv[0][i0];
            #pragma unroll
            for (int nt=0;nt<8;nt++){ rm = fmaxf(rm, Sv[nt][i0]); rm = fmaxf(rm, Sv[nt][i0+1]); }
            rm = fmaxf(rm, __shfl_xor_sync(0xffffffffu, rm, 1));
            rm = fmaxf(rm, __shfl_xor_sync(0xffffffffu, rm, 2));
            const float mn = fmaxf(mrun[hh], rm);
            const float al = ex2f((mrun[hh]-mn)*SC);
            mrun[hh] = mn;
            float sum = 0.f;
            #pragma unroll
            for (int nt=0;nt<8;nt++){
                Sv[nt][i0]   = ex2f((Sv[nt][i0]  -mn)*SC); sum += Sv[nt][i0];
                Sv[nt][i0+1] = ex2f((Sv[nt][i0+1]-mn)*SC); sum += Sv[nt][i0+1];
            }
            sum += __shfl_xor_sync(0xffffffffu, sum, 1);
            sum += __shfl_xor_sync(0xffffffffu, sum, 2);
            lrun[hh] = lrun[hh]*al + sum;
            #pragma unroll
            for (int nt=0;nt<8;nt++){ O[nt][i0] *= al; O[nt][i0+1] *= al; }
        }

        // ---- O += P @ V ----
        #pragma unroll
        for (int kt=0;kt<4;kt++){
            uint32_t ph[4], pl[4];
            split2(Sv[2*kt][0],   Sv[2*kt][1],   ph[0], pl[0]);
            split2(Sv[2*kt][2],   Sv[2*kt][3],   ph[1], pl[1]);
            split2(Sv[2*kt+1][0], Sv[2*kt+1][1], ph[2], pl[2]);
            split2(Sv[2*kt+1][2], Sv[2*kt+1][3], ph[3], pl[3]);
            #pragma unroll
            for (int pr=0;pr<4;pr++){
                uint32_t vh4[4], vl4[4];
                const uint32_t va = sb + 2*GPLANE + swz128(kt*16 + vrow0, pr*2 + (l>>4));
                LDSM4T(vh4, va);
                LDSM4T(vl4, va + GPLANE);
                #pragma unroll
                for (int s2=0;s2<2;s2++){
                    const int nt = pr*2+s2;
                    uint32_t* vh = &vh4[s2*2];
                    uint32_t* vl = &vl4[s2*2];
                    MMA16816(O[nt], ph, vh);
                    MMA16816(O[nt], ph, vl);
                    MMA16816(O[nt], pl, vh);
                }
            }
        }
    }

    // ---- normalize + write hi/lo planes [B,S,D] ----
    const int b = bhid>>4, hhead = bhid&15;
    #pragma unroll
    for (int hh=0;hh<2;hh++){
        const float inv = 1.f / lrun[hh];
        const int row = qt*128 + wm + (l>>2) + hh*8;
        const size_t obase = ((size_t)b*S_ + row)*D_ + hhead*HD_;
        #pragma unroll
        for (int nt=0;nt<8;nt++){
            uint32_t h, lo;
            split2(O[nt][hh*2+0]*inv, O[nt][hh*2+1]*inv, h, lo);
            const size_t o = obase + nt*8 + (l&3)*2;
            *reinterpret_cast<uint32_t*>(&g_ah[o]) = h;
            *reinterpret_cast<uint32_t*>(&g_al[o]) = lo;
        }
    }
    #undef A_ISSUE
}

// ---------------- launch ----------------
extern "C" void kernel_launch(void* const* d_in, const int* in_sizes, int n_in,
                              void* d_out, int out_size)
{
    const float* X  = (const float*)d_in[0];
    const float* Wq = (const float*)d_in[1];
    const float* bq = (const float*)d_in[2];
    const float* Wk = (const float*)d_in[3];
    const float* bk = (const float*)d_in[4];
    const float* Wv = (const float*)d_in[5];
    const float* bv = (const float*)d_in[6];
    const float* Wo = (const float*)d_in[7];
    const float* bo = (const float*)d_in[8];
    float* out = (float*)d_out;

    cudaFuncSetAttribute(qkv_k,  cudaFuncAttributeMaxDynamicSharedMemorySize, GSMEM);
    cudaFuncSetAttribute(out_k,  cudaFuncAttributeMaxDynamicSharedMemorySize, GSMEM);
    cudaFuncSetAttribute(attn_k, cudaFuncAttributeMaxDynamicSharedMemorySize, ASMEM);

    split_x<<<M_*D_/(256*8), 256>>>(X);
    transpose_w<<<dim3(32,32,4), 256>>>(Wq, Wk, Wv, Wo);
    qkv_k<<<dim3(D_/128, M_/128, 3), 256, GSMEM>>>(bq, bk, bv);
    attn_k<<<dim3(S_/128, B_*H_), 256, ASMEM>>>();
    out_k<<<dim3(D_/128, M_/128), 256, GSMEM>>>(bo, out);
}